// round 15
// baseline (speedup 1.0000x reference)
#include <cuda_runtime.h>
#include <cuda_bf16.h>
#include <math.h>
#include <cstdint>

static constexpr float EPS32     = 1.1920928955078125e-07f;
static constexpr float MIN_ENORM = 1e-15f;
static constexpr float CLAMP_V   = 16.635532333438687f;  // log(2/eps32)
static constexpr float SMOOTHB   = 50.0f;
static constexpr float MAXNORM   = 1.0f - 1e-5f;
static constexpr float MAXNORM2  = MAXNORM * MAXNORM;

// ---- smem layout (bytes from dynamic-smem base) ----
// A: 32 rows x 136 bf16 (stride 272B). B: 128 rows x 136 bf16 ([p 0..63][w 64..127]).
#define A_HI_OFF   0u
#define A_LO_OFF   8704u
#define B_HI_OFF   17408u
#define B_LO_OFF   52224u
#define VVS_OFF    87040u
#define C_UU_OFF   87168u
#define C_AS_OFF   87424u
#define C_UA_OFF   87680u
#define C_RN_OFF   87936u
#define C_CF_OFF   88192u
#define SMEM_BYTES 88448

__device__ __forceinline__ uint32_t smem_to_u32(const void* smem_ptr) {
    uint32_t addr;
    asm("{ .reg .u64 tmp; cvta.to.shared.u64 tmp, %1; cvt.u32.u64 %0, tmp; }"
        : "=r"(addr) : "l"(smem_ptr));
    return addr;
}

__device__ __forceinline__ void ldsm4(uint32_t addr, uint32_t r[4]) {
    asm volatile("ldmatrix.sync.aligned.m8n8.x4.shared.b16 {%0,%1,%2,%3}, [%4];"
                 : "=r"(r[0]), "=r"(r[1]), "=r"(r[2]), "=r"(r[3]) : "r"(addr));
}

__device__ __forceinline__ void mma16816(float c[4], const uint32_t a[4],
                                         uint32_t b0, uint32_t b1) {
    asm volatile(
        "mma.sync.aligned.m16n8k16.row.col.f32.bf16.bf16.f32 "
        "{%0,%1,%2,%3}, {%4,%5,%6,%7}, {%8,%9}, {%0,%1,%2,%3};"
        : "+f"(c[0]), "+f"(c[1]), "+f"(c[2]), "+f"(c[3])
        : "r"(a[0]), "r"(a[1]), "r"(a[2]), "r"(a[3]), "r"(b0), "r"(b1));
}

// packed split: float4 -> 4 bf16 hi (8B) + 4 bf16 lo (8B), bf16x2 CVTs
__device__ __forceinline__ void store_split8(char* hi, char* lo, uint32_t off, float4 v) {
    uint32_t h01, h23;
    asm("cvt.rn.bf16x2.f32 %0, %1, %2;" : "=r"(h01) : "f"(v.y), "f"(v.x));
    asm("cvt.rn.bf16x2.f32 %0, %1, %2;" : "=r"(h23) : "f"(v.w), "f"(v.z));
    const float fx = __uint_as_float(h01 << 16);
    const float fy = __uint_as_float(h01 & 0xffff0000u);
    const float fz = __uint_as_float(h23 << 16);
    const float fw = __uint_as_float(h23 & 0xffff0000u);
    uint32_t l01, l23;
    asm("cvt.rn.bf16x2.f32 %0, %1, %2;" : "=r"(l01) : "f"(v.y - fy), "f"(v.x - fx));
    asm("cvt.rn.bf16x2.f32 %0, %1, %2;" : "=r"(l23) : "f"(v.w - fw), "f"(v.z - fz));
    uint2 hv, lv;
    hv.x = h01; hv.y = h23;
    lv.x = l01; lv.y = l23;
    *reinterpret_cast<uint2*>(hi + off) = hv;
    *reinterpret_cast<uint2*>(lo + off) = lv;
}

// ---------------- epilogue math: single-divide form (validated) ----------------
__device__ __forceinline__ float epilogue(float pv, float wacc, float vv,
                                          float uu, float asc, float ua,
                                          float ranorm, float coef) {
    const float av    = asc * wacc;
    const float alpha = 1.0f - 2.0f * pv + vv;
    const float beta  = 1.0f - uu;
    const float den   = fmaxf(1.0f - 2.0f * pv + uu * vv, EPS32);
    const float d2    = den * den;

    const float num_s = alpha * ua + beta * av;
    const float num_q = alpha * alpha * uu - 2.0f * alpha * beta * pv + beta * beta * vv;

    float arg;
    if (num_q > MAXNORM2 * d2) {
        const float suba_c = MAXNORM * num_s * __frsqrt_rn(num_q);
        const float lam_c  = 2.0f / fmaxf(1.0f - MAXNORM2, EPS32);
        arg = lam_c * suba_c * ranorm;
    } else {
        const float numer = 2.0f * num_s * den * ranorm;
        const float denom = fmaxf(d2 - num_q, EPS32 * d2);
        arg = __fdividef(numer, denom);
    }

    float sc;
    if (fabsf(arg) < 16.0f) {
        sc = arg;  // smooth clamp is identity to <1e-14 here
    } else {
        const float z1  = SMOOTHB * (arg + CLAMP_V);
        const float z2  = SMOOTHB * (arg - CLAMP_V);
        const float sp1 = fmaxf(z1, 0.0f) + log1pf(__expf(-fabsf(z1)));
        const float sp2 = fmaxf(z2, 0.0f) + log1pf(__expf(-fabsf(z2)));
        sc = -CLAMP_V + (sp1 - sp2) * (1.0f / SMOOTHB);
    }

    const float s_ = fabsf(sc);
    const float r  = __logf(s_ + sqrtf(fmaf(s_, s_, 1.0f)));   // asinh(|sc|)
    return coef * copysignf(r, sc);
}

// ---------------- fused kernel ----------------
// grid (2, 128): ob = 64-output slice, bb = 32-batch tile. 256 threads = 8 warps.
// ~88KB smem -> 2 CTAs/SM resident; all 256 CTAs in one wave.
// Mainloop: warp w -> m-tile (w&1)*16, n-quarter (w>>1)*16 (P rows nq, W rows nq+64).
__global__ __launch_bounds__(256, 2)
void hyp_mma_kernel(const float* __restrict__ x,
                    const float* __restrict__ w,
                    const float* __restrict__ p,
                    float* __restrict__ out) {
    extern __shared__ __align__(16) char sm[];
    const uint32_t sbase = smem_to_u32(sm);

    const int tid  = threadIdx.x;
    const int wid  = tid >> 5;
    const int lane = tid & 31;
    const int ob   = blockIdx.x;   // 0..1
    const int bb   = blockIdx.y;   // 0..127

    float* vvs = reinterpret_cast<float*>(sm + VVS_OFF);
    float* cU  = reinterpret_cast<float*>(sm + C_UU_OFF);
    float* cAs = reinterpret_cast<float*>(sm + C_AS_OFF);
    float* cUa = reinterpret_cast<float*>(sm + C_UA_OFF);
    float* cRn = reinterpret_cast<float*>(sm + C_RN_OFF);
    float* cCf = reinterpret_cast<float*>(sm + C_CF_OFF);

    // ================= prologue: batched loads (max MLP), split, STS =================
    {
        // A: x tile [32][128]; every thread: 4 float4 (row = tid>>3, 16-col chunk q)
        const int arow = tid >> 3;
        const int aq   = tid & 7;
        const float4* asrc = reinterpret_cast<const float4*>(
            x + (size_t)(bb * 32 + arow) * 128 + aq * 16);
        float4 av0 = asrc[0], av1 = asrc[1], av2 = asrc[2], av3 = asrc[3];

        // B: [p 64; w 64] x 128 cols; every thread: 16 float4 (row = tid>>1, half = tid&1)
        const int brow = tid >> 1;
        const int bq   = tid & 1;
        const float* bsrc_f = (brow < 64)
            ? (p + (size_t)(ob * 64 + brow) * 128 + bq * 64)
            : (w + (size_t)(ob * 64 + brow - 64) * 128 + bq * 64);
        const float4* bsrc = reinterpret_cast<const float4*>(bsrc_f);

        float4 bv[8];
#pragma unroll
        for (int i = 0; i < 8; i++) bv[i] = bsrc[i];        // batch 1 issued

        // A split + vv while B batch 1 in flight
        char* ahi = sm + A_HI_OFF;
        char* alo = sm + A_LO_OFF;
        float ss = av0.x * av0.x + av0.y * av0.y + av0.z * av0.z + av0.w * av0.w;
        ss += av1.x * av1.x + av1.y * av1.y + av1.z * av1.z + av1.w * av1.w;
        ss += av2.x * av2.x + av2.y * av2.y + av2.z * av2.z + av2.w * av2.w;
        ss += av3.x * av3.x + av3.y * av3.y + av3.z * av3.z + av3.w * av3.w;
        store_split8(ahi, alo, (uint32_t)(arow * 272 + (aq * 16 +  0) * 2), av0);
        store_split8(ahi, alo, (uint32_t)(arow * 272 + (aq * 16 +  4) * 2), av1);
        store_split8(ahi, alo, (uint32_t)(arow * 272 + (aq * 16 +  8) * 2), av2);
        store_split8(ahi, alo, (uint32_t)(arow * 272 + (aq * 16 + 12) * 2), av3);
        ss += __shfl_xor_sync(0xffffffffu, ss, 1);
        ss += __shfl_xor_sync(0xffffffffu, ss, 2);
        ss += __shfl_xor_sync(0xffffffffu, ss, 4);
        if (aq == 0) vvs[arow] = ss;

        // B split batch 1, then batch 2
        char* bhi = sm + B_HI_OFF;
        char* blo = sm + B_LO_OFF;
#pragma unroll
        for (int i = 0; i < 8; i++)
            store_split8(bhi, blo, (uint32_t)(brow * 272 + (bq * 64 + i * 4) * 2), bv[i]);
#pragma unroll
        for (int i = 0; i < 8; i++) bv[i] = bsrc[8 + i];    // batch 2 issued
#pragma unroll
        for (int i = 0; i < 8; i++)
            store_split8(bhi, blo, (uint32_t)(brow * 272 + (bq * 64 + 32 + i * 4) * 2), bv[i]);
    }
    __syncthreads();

    // ====== per-o constants from the SMEM B tile (no extra gmem traffic) ======
    // 4 threads per output: quarter-dots over 32 cols, combine via shfl.
    {
        const int ol  = tid >> 2;       // 0..63
        const int qtr = tid & 3;        // 32-col quarter
        const char* bh = sm + B_HI_OFF;
        const char* bl = sm + B_LO_OFF;
        const uint32_t prow = (uint32_t)ol * 272u;
        const uint32_t wrow = (uint32_t)(64 + ol) * 272u;
        float pp = 0.0f, ww = 0.0f, pw = 0.0f;
#pragma unroll
        for (int i = 0; i < 4; i++) {   // 8 cols per iter
            const uint32_t co = (uint32_t)(qtr * 32 + i * 8) * 2u;
            uint4 ph = *reinterpret_cast<const uint4*>(bh + prow + co);
            uint4 pl = *reinterpret_cast<const uint4*>(bl + prow + co);
            uint4 wh = *reinterpret_cast<const uint4*>(bh + wrow + co);
            uint4 wl = *reinterpret_cast<const uint4*>(bl + wrow + co);
#pragma unroll
            for (int u = 0; u < 4; u++) {
                const uint32_t phv = (&ph.x)[u], plv = (&pl.x)[u];
                const uint32_t whv = (&wh.x)[u], wlv = (&wl.x)[u];
                const float p0 = __uint_as_float(phv << 16) + __uint_as_float(plv << 16);
                const float p1 = __uint_as_float(phv & 0xffff0000u) + __uint_as_float(plv & 0xffff0000u);
                const float w0 = __uint_as_float(whv << 16) + __uint_as_float(wlv << 16);
                const float w1 = __uint_as_float(whv & 0xffff0000u) + __uint_as_float(wlv & 0xffff0000u);
                pp += p0 * p0 + p1 * p1;
                ww += w0 * w0 + w1 * w1;
                pw += p0 * w0 + p1 * w1;
            }
        }
        pp += __shfl_xor_sync(0xffffffffu, pp, 1);
        pp += __shfl_xor_sync(0xffffffffu, pp, 2);
        ww += __shfl_xor_sync(0xffffffffu, ww, 1);
        ww += __shfl_xor_sync(0xffffffffu, ww, 2);
        pw += __shfl_xor_sync(0xffffffffu, pw, 1);
        pw += __shfl_xor_sync(0xffffffffu, pw, 2);
        if (qtr == 0) {
            const float uu     = pp;
            const float ascale = fmaxf(1.0f - uu, EPS32);   // 2/lambda_bias
            const float anorm  = fmaxf(ascale * sqrtf(ww), MIN_ENORM);
            cU[ol]  = uu;
            cAs[ol] = ascale;
            cUa[ol] = -ascale * pw;
            cRn[ol] = 1.0f / anorm;
            cCf[ol] = (2.0f / fmaxf(1.0f - uu, EPS32)) * anorm;
        }
    }
    __syncthreads();

    // ---- ldmatrix address prep ----
    const int mt   = wid & 1;              // m-tile (16 rows of 32)
    const int nq   = (wid >> 1) * 16;      // n-quarter (16 of 64 outputs)
    const int r8   = (lane & 7) + ((lane >> 3) & 1) * 8;
    const int koff = (lane >> 4) * 8;
    const uint32_t aOff = (uint32_t)((mt * 16 + r8) * 272 + koff * 2);
    const uint32_t bpO  = (uint32_t)((nq + r8) * 272 + koff * 2);
    const uint32_t bwO  = (uint32_t)((nq + 64 + r8) * 272 + koff * 2);

    float accP[2][4], accW[2][4];
#pragma unroll
    for (int j = 0; j < 2; j++)
#pragma unroll
        for (int c = 0; c < 4; c++) { accP[j][c] = 0.0f; accW[j][c] = 0.0f; }

    // ---- mainloop: 3 split terms (hi*hi, hi*lo, lo*hi), 8 k-steps each ----
#pragma unroll 1
    for (int term = 0; term < 3; term++) {
        const uint32_t aBase = sbase + (term == 2 ? A_LO_OFF : A_HI_OFF);
        const uint32_t bBase = sbase + (term == 1 ? B_LO_OFF : B_HI_OFF);
#pragma unroll 4
        for (int ks = 0; ks < 8; ks++) {
            const uint32_t kb = (uint32_t)ks * 32u;
            uint32_t a[4], bp[4], bw4[4];
            ldsm4(aBase + aOff + kb, a);
            ldsm4(bBase + bpO + kb, bp);
            ldsm4(bBase + bwO + kb, bw4);
            mma16816(accP[0], a, bp[0], bp[2]);
            mma16816(accP[1], a, bp[1], bp[3]);
            mma16816(accW[0], a, bw4[0], bw4[2]);
            mma16816(accW[1], a, bw4[1], bw4[3]);
        }
    }

    // ---- epilogue: thread holds D rows m0, m0+8; cols q*2, q*2+1 per n8 tile ----
    {
        const int m0 = mt * 16 + (lane >> 2);
        const int q  = lane & 3;
        const float vv0 = vvs[m0];
        const float vv1 = vvs[m0 + 8];
        const size_t bG0 = (size_t)(bb * 32 + m0) * 128;
        const size_t bG1 = (size_t)(bb * 32 + m0 + 8) * 128;
#pragma unroll
        for (int j = 0; j < 2; j++) {
            const int ol0 = nq + j * 8 + q * 2;
            const int ol1 = ol0 + 1;
            const int og0 = ob * 64 + ol0;
            const float u0 = cU[ol0],  u1 = cU[ol1];
            const float s0 = cAs[ol0], s1 = cAs[ol1];
            const float a0 = cUa[ol0], a1 = cUa[ol1];
            const float r0 = cRn[ol0], r1 = cRn[ol1];
            const float f0 = cCf[ol0], f1 = cCf[ol1];

            float2 e0, e1;
            e0.x = epilogue(accP[j][0], accW[j][0], vv0, u0, s0, a0, r0, f0);
            e0.y = epilogue(accP[j][1], accW[j][1], vv0, u1, s1, a1, r1, f1);
            e1.x = epilogue(accP[j][2], accW[j][2], vv1, u0, s0, a0, r0, f0);
            e1.y = epilogue(accP[j][3], accW[j][3], vv1, u1, s1, a1, r1, f1);

            *reinterpret_cast<float2*>(out + bG0 + og0) = e0;
            *reinterpret_cast<float2*>(out + bG1 + og0) = e1;
        }
    }
}

extern "C" void kernel_launch(void* const* d_in, const int* in_sizes, int n_in,
                              void* d_out, int out_size) {
    const float* x = (const float*)d_in[0];   // [4096, 128]
    const float* w = (const float*)d_in[1];   // [128, 128] weight
    const float* p = (const float*)d_in[2];   // [128, 128] bias
    float* out = (float*)d_out;               // [4096, 128]

    cudaFuncSetAttribute(hyp_mma_kernel,
                         cudaFuncAttributeMaxDynamicSharedMemorySize, SMEM_BYTES);
    dim3 grid(2, 128);
    hyp_mma_kernel<<<grid, 256, SMEM_BYTES>>>(x, w, p, out);
}

// round 17
// speedup vs baseline: 1.4636x; 1.4636x over previous
#include <cuda_runtime.h>
#include <cuda_bf16.h>
#include <math.h>
#include <cstdint>

static constexpr float EPS32     = 1.1920928955078125e-07f;
static constexpr float MIN_ENORM = 1e-15f;
static constexpr float CLAMP_V   = 16.635532333438687f;  // log(2/eps32)
static constexpr float SMOOTHB   = 50.0f;
static constexpr float MAXNORM   = 1.0f - 1e-5f;
static constexpr float MAXNORM2  = MAXNORM * MAXNORM;

// ---- smem layout (bytes from dynamic-smem base) ----
// A: 64 rows x 136 bf16 (stride 272B). B: 128 rows x 136 bf16 ([p 0..63][w 64..127]).
#define A_HI_OFF   0u
#define A_LO_OFF   17408u
#define B_HI_OFF   34816u
#define B_LO_OFF   69632u
#define VVS_OFF    104448u
#define C_UU_OFF   104704u
#define C_AS_OFF   104960u
#define C_UA_OFF   105216u
#define C_RN_OFF   105472u
#define C_CF_OFF   105728u
#define SMEM_BYTES 105984

__device__ __forceinline__ uint32_t smem_to_u32(const void* smem_ptr) {
    uint32_t addr;
    asm("{ .reg .u64 tmp; cvta.to.shared.u64 tmp, %1; cvt.u32.u64 %0, tmp; }"
        : "=r"(addr) : "l"(smem_ptr));
    return addr;
}

__device__ __forceinline__ void ldsm4(uint32_t addr, uint32_t r[4]) {
    asm volatile("ldmatrix.sync.aligned.m8n8.x4.shared.b16 {%0,%1,%2,%3}, [%4];"
                 : "=r"(r[0]), "=r"(r[1]), "=r"(r[2]), "=r"(r[3]) : "r"(addr));
}

__device__ __forceinline__ void mma16816(float c[4], const uint32_t a[4],
                                         uint32_t b0, uint32_t b1) {
    asm volatile(
        "mma.sync.aligned.m16n8k16.row.col.f32.bf16.bf16.f32 "
        "{%0,%1,%2,%3}, {%4,%5,%6,%7}, {%8,%9}, {%0,%1,%2,%3};"
        : "+f"(c[0]), "+f"(c[1]), "+f"(c[2]), "+f"(c[3])
        : "r"(a[0]), "r"(a[1]), "r"(a[2]), "r"(a[3]), "r"(b0), "r"(b1));
}

// packed split: float4 -> 4 bf16 hi (8B) + 4 bf16 lo (8B), bf16x2 CVTs
__device__ __forceinline__ void store_split8(char* hi, char* lo, uint32_t off, float4 v) {
    uint32_t h01, h23;
    asm("cvt.rn.bf16x2.f32 %0, %1, %2;" : "=r"(h01) : "f"(v.y), "f"(v.x));
    asm("cvt.rn.bf16x2.f32 %0, %1, %2;" : "=r"(h23) : "f"(v.w), "f"(v.z));
    const float fx = __uint_as_float(h01 << 16);
    const float fy = __uint_as_float(h01 & 0xffff0000u);
    const float fz = __uint_as_float(h23 << 16);
    const float fw = __uint_as_float(h23 & 0xffff0000u);
    uint32_t l01, l23;
    asm("cvt.rn.bf16x2.f32 %0, %1, %2;" : "=r"(l01) : "f"(v.y - fy), "f"(v.x - fx));
    asm("cvt.rn.bf16x2.f32 %0, %1, %2;" : "=r"(l23) : "f"(v.w - fw), "f"(v.z - fz));
    uint2 hv, lv;
    hv.x = h01; hv.y = h23;
    lv.x = l01; lv.y = l23;
    *reinterpret_cast<uint2*>(hi + off) = hv;
    *reinterpret_cast<uint2*>(lo + off) = lv;
}

// ---------------- epilogue math: single-divide form (validated) ----------------
__device__ __forceinline__ float epilogue(float pv, float wacc, float vv,
                                          float uu, float asc, float ua,
                                          float ranorm, float coef) {
    const float av    = asc * wacc;
    const float alpha = 1.0f - 2.0f * pv + vv;
    const float beta  = 1.0f - uu;
    const float den   = fmaxf(1.0f - 2.0f * pv + uu * vv, EPS32);
    const float d2    = den * den;

    const float num_s = alpha * ua + beta * av;
    const float num_q = alpha * alpha * uu - 2.0f * alpha * beta * pv + beta * beta * vv;

    float arg;
    if (num_q > MAXNORM2 * d2) {
        const float suba_c = MAXNORM * num_s * __frsqrt_rn(num_q);
        const float lam_c  = 2.0f / fmaxf(1.0f - MAXNORM2, EPS32);
        arg = lam_c * suba_c * ranorm;
    } else {
        const float numer = 2.0f * num_s * den * ranorm;
        const float denom = fmaxf(d2 - num_q, EPS32 * d2);
        arg = __fdividef(numer, denom);
    }

    float sc;
    if (fabsf(arg) < 16.0f) {
        sc = arg;  // smooth clamp is identity to <1e-14 here
    } else {
        const float z1  = SMOOTHB * (arg + CLAMP_V);
        const float z2  = SMOOTHB * (arg - CLAMP_V);
        const float sp1 = fmaxf(z1, 0.0f) + log1pf(__expf(-fabsf(z1)));
        const float sp2 = fmaxf(z2, 0.0f) + log1pf(__expf(-fabsf(z2)));
        sc = -CLAMP_V + (sp1 - sp2) * (1.0f / SMOOTHB);
    }

    const float s_ = fabsf(sc);
    const float r  = __logf(s_ + sqrtf(fmaf(s_, s_, 1.0f)));   // asinh(|sc|)
    return coef * copysignf(r, sc);
}

// ---------------- fused kernel ----------------
// grid (2, 64): ob = 64-output slice, bb = 64-batch tile. 256 threads = 8 warps.
// Warp tile m32 x n16 (P and W): warps = 2 m-tiles x 4 n-tiles.
// Fragment-shared mainloop: 8 ldsm4 -> 24 MMA per k-step (1:3 vs R8's 3:4).
__global__ __launch_bounds__(256, 1)
void hyp_mma_kernel(const float* __restrict__ x,
                    const float* __restrict__ w,
                    const float* __restrict__ p,
                    float* __restrict__ out) {
    extern __shared__ __align__(16) char sm[];
    const uint32_t sbase = smem_to_u32(sm);

    const int tid  = threadIdx.x;
    const int wid  = tid >> 5;
    const int lane = tid & 31;
    const int ob   = blockIdx.x;   // 0..1
    const int bb   = blockIdx.y;   // 0..63

    float* vvs = reinterpret_cast<float*>(sm + VVS_OFF);
    float* cU  = reinterpret_cast<float*>(sm + C_UU_OFF);
    float* cAs = reinterpret_cast<float*>(sm + C_AS_OFF);
    float* cUa = reinterpret_cast<float*>(sm + C_UA_OFF);
    float* cRn = reinterpret_cast<float*>(sm + C_RN_OFF);
    float* cCf = reinterpret_cast<float*>(sm + C_CF_OFF);

    // ================= prologue: batched loads (max MLP), split, STS =================
    {
        // A: x tile [64][128]; thread: row = tid>>2, 32-col chunk aq = tid&3 (8 float4)
        const int arow = tid >> 2;
        const int aq   = tid & 3;
        const float4* asrc = reinterpret_cast<const float4*>(
            x + (size_t)(bb * 64 + arow) * 128 + aq * 32);
        float4 av[8];
#pragma unroll
        for (int i = 0; i < 8; i++) av[i] = asrc[i];

        // B: [p 64; w 64] rows; thread: row = tid>>1, half bq = tid&1 (16 float4)
        const int brow = tid >> 1;
        const int bq   = tid & 1;
        const float* bsrc_f = (brow < 64)
            ? (p + (size_t)(ob * 64 + brow) * 128 + bq * 64)
            : (w + (size_t)(ob * 64 + brow - 64) * 128 + bq * 64);
        const float4* bsrc = reinterpret_cast<const float4*>(bsrc_f);
        float4 bv[8];
#pragma unroll
        for (int i = 0; i < 8; i++) bv[i] = bsrc[i];        // B batch 1 in flight

        // A split + vv while B batch 1 lands
        char* ahi = sm + A_HI_OFF;
        char* alo = sm + A_LO_OFF;
        float ss = 0.0f;
#pragma unroll
        for (int i = 0; i < 8; i++) {
            ss += av[i].x * av[i].x + av[i].y * av[i].y
                + av[i].z * av[i].z + av[i].w * av[i].w;
            store_split8(ahi, alo, (uint32_t)(arow * 272 + (aq * 32 + i * 4) * 2), av[i]);
        }
        ss += __shfl_xor_sync(0xffffffffu, ss, 1);
        ss += __shfl_xor_sync(0xffffffffu, ss, 2);
        if (aq == 0) vvs[arow] = ss;

        // B split batch 1, issue batch 2, split batch 2
        char* bhi = sm + B_HI_OFF;
        char* blo = sm + B_LO_OFF;
#pragma unroll
        for (int i = 0; i < 8; i++)
            store_split8(bhi, blo, (uint32_t)(brow * 272 + (bq * 64 + i * 4) * 2), bv[i]);
#pragma unroll
        for (int i = 0; i < 8; i++) bv[i] = bsrc[8 + i];
#pragma unroll
        for (int i = 0; i < 8; i++)
            store_split8(bhi, blo, (uint32_t)(brow * 272 + (bq * 64 + 32 + i * 4) * 2), bv[i]);
    }
    __syncthreads();

    // ====== per-o constants from the SMEM B tile (4 threads per output) ======
    {
        const int ol  = tid >> 2;       // 0..63
        const int qtr = tid & 3;        // 32-col quarter
        const char* bh = sm + B_HI_OFF;
        const char* bl = sm + B_LO_OFF;
        const uint32_t prow = (uint32_t)ol * 272u;
        const uint32_t wrow = (uint32_t)(64 + ol) * 272u;
        float pp = 0.0f, ww = 0.0f, pw = 0.0f;
#pragma unroll
        for (int i = 0; i < 4; i++) {   // 8 cols per iter
            const uint32_t co = (uint32_t)(qtr * 32 + i * 8) * 2u;
            uint4 ph = *reinterpret_cast<const uint4*>(bh + prow + co);
            uint4 pl = *reinterpret_cast<const uint4*>(bl + prow + co);
            uint4 wh = *reinterpret_cast<const uint4*>(bh + wrow + co);
            uint4 wl = *reinterpret_cast<const uint4*>(bl + wrow + co);
#pragma unroll
            for (int u = 0; u < 4; u++) {
                const uint32_t phv = (&ph.x)[u], plv = (&pl.x)[u];
                const uint32_t whv = (&wh.x)[u], wlv = (&wl.x)[u];
                const float p0 = __uint_as_float(phv << 16) + __uint_as_float(plv << 16);
                const float p1 = __uint_as_float(phv & 0xffff0000u) + __uint_as_float(plv & 0xffff0000u);
                const float w0 = __uint_as_float(whv << 16) + __uint_as_float(wlv << 16);
                const float w1 = __uint_as_float(whv & 0xffff0000u) + __uint_as_float(wlv & 0xffff0000u);
                pp += p0 * p0 + p1 * p1;
                ww += w0 * w0 + w1 * w1;
                pw += p0 * w0 + p1 * w1;
            }
        }
        pp += __shfl_xor_sync(0xffffffffu, pp, 1);
        pp += __shfl_xor_sync(0xffffffffu, pp, 2);
        ww += __shfl_xor_sync(0xffffffffu, ww, 1);
        ww += __shfl_xor_sync(0xffffffffu, ww, 2);
        pw += __shfl_xor_sync(0xffffffffu, pw, 1);
        pw += __shfl_xor_sync(0xffffffffu, pw, 2);
        if (qtr == 0) {
            const float uu     = pp;
            const float ascale = fmaxf(1.0f - uu, EPS32);   // 2/lambda_bias
            const float anorm  = fmaxf(ascale * sqrtf(ww), MIN_ENORM);
            cU[ol]  = uu;
            cAs[ol] = ascale;
            cUa[ol] = -ascale * pw;
            cRn[ol] = 1.0f / anorm;
            cCf[ol] = (2.0f / fmaxf(1.0f - uu, EPS32)) * anorm;
        }
    }
    __syncthreads();

    // ---- ldmatrix address prep: warp tile m32 (mt) x n16 (nt) ----
    const int mt   = wid & 1;              // m-tile: rows mt*32 .. mt*32+31
    const int nt   = wid >> 1;             // n-tile: outs nt*16 .. nt*16+15
    const int r8   = (lane & 7) + ((lane >> 3) & 1) * 8;
    const int koff = (lane >> 4) * 8;
    const uint32_t aOff0 = (uint32_t)((mt * 32 + r8) * 272 + koff * 2);
    const uint32_t aOff1 = aOff0 + 16u * 272u;
    const uint32_t bpO   = (uint32_t)((nt * 16 + r8) * 272 + koff * 2);
    const uint32_t bwO   = bpO + 64u * 272u;

    // accumulators: [am m16-tile][bn n8-tile][4]
    float accP[2][2][4], accW[2][2][4];
#pragma unroll
    for (int am = 0; am < 2; am++)
#pragma unroll
        for (int bn = 0; bn < 2; bn++)
#pragma unroll
            for (int c = 0; c < 4; c++) { accP[am][bn][c] = 0.0f; accW[am][bn][c] = 0.0f; }

    // ---- mainloop: fragment-shared. 8 ldsm4 + 24 MMA per k-step ----
#pragma unroll 2
    for (int ks = 0; ks < 8; ks++) {
        const uint32_t kb = (uint32_t)ks * 32u;
        uint32_t ah0[4], ah1[4], al0[4], al1[4];
        uint32_t bph[4], bwh[4], bpl[4], bwl[4];
        ldsm4(sbase + A_HI_OFF + aOff0 + kb, ah0);
        ldsm4(sbase + A_HI_OFF + aOff1 + kb, ah1);
        ldsm4(sbase + A_LO_OFF + aOff0 + kb, al0);
        ldsm4(sbase + A_LO_OFF + aOff1 + kb, al1);
        ldsm4(sbase + B_HI_OFF + bpO + kb, bph);
        ldsm4(sbase + B_HI_OFF + bwO + kb, bwh);
        ldsm4(sbase + B_LO_OFF + bpO + kb, bpl);
        ldsm4(sbase + B_LO_OFF + bwO + kb, bwl);

        // term hi*hi
        mma16816(accP[0][0], ah0, bph[0], bph[2]);
        mma16816(accP[0][1], ah0, bph[1], bph[3]);
        mma16816(accP[1][0], ah1, bph[0], bph[2]);
        mma16816(accP[1][1], ah1, bph[1], bph[3]);
        mma16816(accW[0][0], ah0, bwh[0], bwh[2]);
        mma16816(accW[0][1], ah0, bwh[1], bwh[3]);
        mma16816(accW[1][0], ah1, bwh[0], bwh[2]);
        mma16816(accW[1][1], ah1, bwh[1], bwh[3]);
        // term hi*lo
        mma16816(accP[0][0], ah0, bpl[0], bpl[2]);
        mma16816(accP[0][1], ah0, bpl[1], bpl[3]);
        mma16816(accP[1][0], ah1, bpl[0], bpl[2]);
        mma16816(accP[1][1], ah1, bpl[1], bpl[3]);
        mma16816(accW[0][0], ah0, bwl[0], bwl[2]);
        mma16816(accW[0][1], ah0, bwl[1], bwl[3]);
        mma16816(accW[1][0], ah1, bwl[0], bwl[2]);
        mma16816(accW[1][1], ah1, bwl[1], bwl[3]);
        // term lo*hi
        mma16816(accP[0][0], al0, bph[0], bph[2]);
        mma16816(accP[0][1], al0, bph[1], bph[3]);
        mma16816(accP[1][0], al1, bph[0], bph[2]);
        mma16816(accP[1][1], al1, bph[1], bph[3]);
        mma16816(accW[0][0], al0, bwh[0], bwh[2]);
        mma16816(accW[0][1], al0, bwh[1], bwh[3]);
        mma16816(accW[1][0], al1, bwh[0], bwh[2]);
        mma16816(accW[1][1], al1, bwh[1], bwh[3]);
    }

    // ---- epilogue: 16 outputs/thread ----
    {
        const int q = lane & 3;
#pragma unroll
        for (int am = 0; am < 2; am++) {
            const int m0 = mt * 32 + am * 16 + (lane >> 2);
            const float vv0 = vvs[m0];
            const float vv1 = vvs[m0 + 8];
            const size_t bG0 = (size_t)(bb * 64 + m0) * 128;
            const size_t bG1 = (size_t)(bb * 64 + m0 + 8) * 128;
#pragma unroll
            for (int bn = 0; bn < 2; bn++) {
                const int ol0 = nt * 16 + bn * 8 + q * 2;
                const int ol1 = ol0 + 1;
                const int og0 = ob * 64 + ol0;
                const float u0 = cU[ol0],  u1 = cU[ol1];
                const float s0 = cAs[ol0], s1 = cAs[ol1];
                const float a0 = cUa[ol0], a1 = cUa[ol1];
                const float r0 = cRn[ol0], r1 = cRn[ol1];
                const float f0 = cCf[ol0], f1 = cCf[ol1];

                float2 e0, e1;
                e0.x = epilogue(accP[am][bn][0], accW[am][bn][0], vv0, u0, s0, a0, r0, f0);
                e0.y = epilogue(accP[am][bn][1], accW[am][bn][1], vv0, u1, s1, a1, r1, f1);
                e1.x = epilogue(accP[am][bn][2], accW[am][bn][2], vv1, u0, s0, a0, r0, f0);
                e1.y = epilogue(accP[am][bn][3], accW[am][bn][3], vv1, u1, s1, a1, r1, f1);

                *reinterpret_cast<float2*>(out + bG0 + og0) = e0;
                *reinterpret_cast<float2*>(out + bG1 + og0) = e1;
            }
        }
    }
}

extern "C" void kernel_launch(void* const* d_in, const int* in_sizes, int n_in,
                              void* d_out, int out_size) {
    const float* x = (const float*)d_in[0];   // [4096, 128]
    const float* w = (const float*)d_in[1];   // [128, 128] weight
    const float* p = (const float*)d_in[2];   // [128, 128] bias
    float* out = (float*)d_out;               // [4096, 128]

    cudaFuncSetAttribute(hyp_mma_kernel,
                         cudaFuncAttributeMaxDynamicSharedMemorySize, SMEM_BYTES);
    dim3 grid(2, 64);
    hyp_mma_kernel<<<grid, 256, SMEM_BYTES>>>(x, w, p, out);
}